// round 17
// baseline (speedup 1.0000x reference)
#include <cuda_runtime.h>
#include <cuda_bf16.h>
#include <stdint.h>

#define NSP   4096
#define CCH   64
#define BATCH 4
#define KT    128
#define NTILES (NSP / KT)
#define NQT   (NSP / 128)      // 32 q-tiles
#define NSPLIT 3               // 384 CTAs = single wave at 3 CTAs/SM

// ---------------------------------------------------------------------------
// Scratch
// ---------------------------------------------------------------------------
__device__ float         g_q [BATCH * NSP * 8];
__device__ uint32_t      g_kp[BATCH * NSP * 8];
__device__ __nv_bfloat16 g_v [(size_t)BATCH * CCH * NSP];
__device__ float         g_po[(size_t)NSPLIT * BATCH * NQT * CCH * 128];
__device__ float         g_pl[NSPLIT * BATCH * NQT * 128];
__device__ int           g_sem[BATCH * NQT];   // zero-init; self-resetting

#define LOG2E 1.4426950408889634f

__device__ __forceinline__ void mma_16x8x16(
    float c[4], uint32_t a0, uint32_t a1, uint32_t a2, uint32_t a3,
    uint32_t b0, uint32_t b1)
{
    asm volatile(
        "mma.sync.aligned.m16n8k16.row.col.f32.bf16.bf16.f32 "
        "{%0,%1,%2,%3}, {%4,%5,%6,%7}, {%8,%9}, {%0,%1,%2,%3};"
        : "+f"(c[0]), "+f"(c[1]), "+f"(c[2]), "+f"(c[3])
        : "r"(a0), "r"(a1), "r"(a2), "r"(a3), "r"(b0), "r"(b1));
}
__device__ __forceinline__ void mma_16x8x8(
    float c[4], uint32_t a0, uint32_t a1, uint32_t b0)
{
    asm volatile(
        "mma.sync.aligned.m16n8k8.row.col.f32.bf16.bf16.f32 "
        "{%0,%1,%2,%3}, {%4,%5}, {%6}, {%0,%1,%2,%3};"
        : "+f"(c[0]), "+f"(c[1]), "+f"(c[2]), "+f"(c[3])
        : "r"(a0), "r"(a1), "r"(b0));
}
__device__ __forceinline__ void ldsm_x4(
    uint32_t& r0, uint32_t& r1, uint32_t& r2, uint32_t& r3, uint32_t addr)
{
    asm volatile("ldmatrix.sync.aligned.m8n8.x4.shared.b16 {%0,%1,%2,%3}, [%4];"
        : "=r"(r0), "=r"(r1), "=r"(r2), "=r"(r3) : "r"(addr));
}
__device__ __forceinline__ void ldsm_x4_t(
    uint32_t& r0, uint32_t& r1, uint32_t& r2, uint32_t& r3, uint32_t addr)
{
    asm volatile("ldmatrix.sync.aligned.m8n8.x4.trans.shared.b16 {%0,%1,%2,%3}, [%4];"
        : "=r"(r0), "=r"(r1), "=r"(r2), "=r"(r3) : "r"(addr));
}
__device__ __forceinline__ uint32_t cvt_bf16x2(float hi, float lo) {
    uint32_t r;
    asm("cvt.rn.bf16x2.f32 %0, %1, %2;" : "=r"(r) : "f"(hi), "f"(lo));
    return r;
}
__device__ __forceinline__ float ex2f(float x) {
    float r;
    asm("ex2.approx.f32 %0, %1;" : "=f"(r) : "f"(x));
    return r;
}
__device__ __forceinline__ void split_bf16(float v, uint16_t& h, uint16_t& l) {
    __nv_bfloat16 hb = __float2bfloat16(v);
    __nv_bfloat16 lb = __float2bfloat16(v - __bfloat162float(hb));
    h = __bfloat16_as_ushort(hb);
    l = __bfloat16_as_ushort(lb);
}
__device__ __forceinline__ uint32_t smem_u32(const void* p) {
    uint32_t a;
    asm("{ .reg .u64 t; cvta.to.shared.u64 t, %1; cvt.u32.u64 %0, t; }"
        : "=r"(a) : "l"(p));
    return a;
}
__device__ __forceinline__ void cp_async16(uint32_t dst, const void* src) {
    asm volatile("cp.async.cg.shared.global [%0], [%1], 16;"
                 :: "r"(dst), "l"(src));
}
#define CP_COMMIT() asm volatile("cp.async.commit_group;" ::: "memory")
#define CP_WAIT0()  asm volatile("cp.async.wait_group 0;" ::: "memory")

// ---------------------------------------------------------------------------
// Projection v7b (unchanged): tensor-core GEMM, ldmatrix-aligned strides.
// ---------------------------------------------------------------------------
#define WS_STR 72
#define XT_STR 72
#define QK_STR 68

__global__ __launch_bounds__(256) void proj_kernel(
    const float* __restrict__ x,
    const float* __restrict__ wq, const float* __restrict__ bq,
    const float* __restrict__ wk, const float* __restrict__ bk,
    const float* __restrict__ wv, const float* __restrict__ bv)
{
    __shared__ __align__(16) uint16_t wh_s[80 * WS_STR];
    __shared__ __align__(16) uint16_t wl_s[80 * WS_STR];
    __shared__ __align__(16) uint16_t xh_s[64 * XT_STR];
    __shared__ __align__(16) uint16_t xl_s[64 * XT_STR];
    __shared__ __align__(16) float    qk_s[16 * QK_STR];
    __shared__ float b_s[80];

    const int tid  = threadIdx.x;
    const int lane = tid & 31;
    const int wrp  = tid >> 5;
    const int g    = lane >> 2;
    const int tg   = lane & 3;
    const int b    = blockIdx.y;
    const int n0   = blockIdx.x * 64;

    #pragma unroll
    for (int i = 0; i < 10; i++) {
        int idx = tid + i * 256;
        int o = idx >> 5, c = (idx & 31) * 2;
        float2 w2;
        if (o < 8)       w2 = *(const float2*)(wq + o * 64 + c);
        else if (o < 16) w2 = *(const float2*)(wk + (o - 8) * 64 + c);
        else             w2 = *(const float2*)(wv + (o - 16) * 64 + c);
        uint16_t h0, l0, h1, l1;
        split_bf16(w2.x, h0, l0); split_bf16(w2.y, h1, l1);
        *(uint32_t*)(wh_s + o * WS_STR + c) = (uint32_t)h0 | ((uint32_t)h1 << 16);
        *(uint32_t*)(wl_s + o * WS_STR + c) = (uint32_t)l0 | ((uint32_t)l1 << 16);
    }
    if (tid < 8)       b_s[tid] = bq[tid];
    else if (tid < 16) b_s[tid] = bk[tid - 8];
    else if (tid < 80) b_s[tid] = bv[tid - 16];

    {
        const float* xb = x + (size_t)b * CCH * NSP + n0;
        #pragma unroll
        for (int i = 0; i < 4; i++) {
            int idx = tid + i * 256;
            int c = idx >> 4, nq = (idx & 15) * 4;
            float4 v = *(const float4*)(xb + (size_t)c * NSP + nq);
            uint16_t h0, l0, h1, l1, h2, l2, h3, l3;
            split_bf16(v.x, h0, l0); split_bf16(v.y, h1, l1);
            split_bf16(v.z, h2, l2); split_bf16(v.w, h3, l3);
            *(uint32_t*)(xh_s + c * XT_STR + nq)     = (uint32_t)h0 | ((uint32_t)h1 << 16);
            *(uint32_t*)(xh_s + c * XT_STR + nq + 2) = (uint32_t)h2 | ((uint32_t)h3 << 16);
            *(uint32_t*)(xl_s + c * XT_STR + nq)     = (uint32_t)l0 | ((uint32_t)l1 << 16);
            *(uint32_t*)(xl_s + c * XT_STR + nq + 2) = (uint32_t)l2 | ((uint32_t)l3 << 16);
        }
    }
    __syncthreads();

    const int lm_m  = lane >> 3;
    const int lm_rl = lane & 7;
    const uint32_t wh_base = smem_u32(wh_s);
    const uint32_t wl_base = smem_u32(wl_s);
    const uint32_t xh_base = smem_u32(xh_s);
    const uint32_t xl_base = smem_u32(xl_s);
    const uint32_t a_off = (uint32_t)((((lm_m & 1) * 8 + lm_rl) * WS_STR + (lm_m >> 1) * 8) * 2);
    const uint32_t b_off = (uint32_t)((((lm_m & 1) * 8 + lm_rl + (lm_m >> 1) * 16) * XT_STR + wrp * 8) * 2);

    float C[5][4];
    #pragma unroll
    for (int mt = 0; mt < 5; mt++)
        #pragma unroll
        for (int i = 0; i < 4; i++) C[mt][i] = 0.f;

    #pragma unroll
    for (int kp = 0; kp < 2; kp++) {
        uint32_t bh[2][2], bl[2][2];
        ldsm_x4_t(bh[0][0], bh[0][1], bh[1][0], bh[1][1],
                  xh_base + b_off + (uint32_t)(32 * kp * XT_STR * 2));
        ldsm_x4_t(bl[0][0], bl[0][1], bl[1][0], bl[1][1],
                  xl_base + b_off + (uint32_t)(32 * kp * XT_STR * 2));
        #pragma unroll
        for (int kk = 0; kk < 2; kk++) {
            const int ks = 2 * kp + kk;
            #pragma unroll
            for (int mt = 0; mt < 5; mt++) {
                const uint32_t astep = (uint32_t)((16 * mt * WS_STR + 16 * ks) * 2);
                uint32_t ah0, ah1, ah2, ah3, al0, al1, al2, al3;
                ldsm_x4(ah0, ah1, ah2, ah3, wh_base + a_off + astep);
                ldsm_x4(al0, al1, al2, al3, wl_base + a_off + astep);
                mma_16x8x16(C[mt], ah0, ah1, ah2, ah3, bh[kk][0], bh[kk][1]);
                mma_16x8x16(C[mt], ah0, ah1, ah2, ah3, bl[kk][0], bl[kk][1]);
                mma_16x8x16(C[mt], al0, al1, al2, al3, bh[kk][0], bh[kk][1]);
            }
        }
    }

    #pragma unroll
    for (int mt = 0; mt < 5; mt++) {
        const float blo = b_s[16 * mt + g];
        const float bhi = b_s[16 * mt + g + 8];
        C[mt][0] += blo; C[mt][1] += blo;
        C[mt][2] += bhi; C[mt][3] += bhi;
    }

    __nv_bfloat16* vb = g_v + (size_t)b * CCH * NSP;
    const int nv = n0 + wrp * 8 + 2 * tg;
    #pragma unroll
    for (int mt = 1; mt < 5; mt++) {
        const int ch = 16 * mt + g - 16;
        *(uint32_t*)(vb + (size_t)ch * NSP + nv)       = cvt_bf16x2(C[mt][1], C[mt][0]);
        *(uint32_t*)(vb + (size_t)(ch + 8) * NSP + nv) = cvt_bf16x2(C[mt][3], C[mt][2]);
    }

    {
        const int nl = wrp * 8 + 2 * tg;
        *(float2*)(qk_s + g * QK_STR + nl)       = make_float2(C[0][0], C[0][1]);
        *(float2*)(qk_s + (g + 8) * QK_STR + nl) = make_float2(C[0][2], C[0][3]);
    }
    __syncthreads();

    if (tid < 64) {
        const int nl = tid;
        float* qp = g_q + ((size_t)b * NSP + n0 + nl) * 8;
        float4 q0, q1;
        q0.x = qk_s[0 * QK_STR + nl] * LOG2E;
        q0.y = qk_s[1 * QK_STR + nl] * LOG2E;
        q0.z = qk_s[2 * QK_STR + nl] * LOG2E;
        q0.w = qk_s[3 * QK_STR + nl] * LOG2E;
        q1.x = qk_s[4 * QK_STR + nl] * LOG2E;
        q1.y = qk_s[5 * QK_STR + nl] * LOG2E;
        q1.z = qk_s[6 * QK_STR + nl] * LOG2E;
        q1.w = qk_s[7 * QK_STR + nl] * LOG2E;
        ((float4*)qp)[0] = q0;
        ((float4*)qp)[1] = q1;
    } else if (tid < 128) {
        const int nl = tid - 64;
        uint16_t kh[8], kl[8];
        #pragma unroll
        for (int i = 0; i < 8; i++)
            split_bf16(qk_s[(8 + i) * QK_STR + nl], kh[i], kl[i]);
        uint32_t row[8];
        #pragma unroll
        for (int i = 0; i < 4; i++) {
            row[i]     = (uint32_t)kh[2*i] | ((uint32_t)kh[2*i+1] << 16);
            row[4 + i] = (uint32_t)kl[2*i] | ((uint32_t)kl[2*i+1] << 16);
        }
        uint4* kp = (uint4*)(g_kp + ((size_t)b * NSP + n0 + nl) * 8);
        kp[0] = ((uint4*)row)[0];
        kp[1] = ((uint4*)row)[1];
    }
}

// ---------------------------------------------------------------------------
// Split-KV flash attention, NSPLIT=3: grid (32,4,3) = 384 CTAs = ONE wave at
// 3 CTAs/SM capacity (no tail wave, unlike NSPLIT=4's 512 CTAs > 444 cap).
// Tile split 11/11/10 per sp. Fused finisher: last-arriving CTA of each
// (b,qt) sums ALL three partials in fixed sp order (deterministic).
// ---------------------------------------------------------------------------
#define K_STR 48
#define V_STR 272
#define KBUF_SZ (128 * K_STR)
#define VBUF_SZ (64 * V_STR)
#define VBASE   (2 * KBUF_SZ)
#define SMEM_SZ (VBASE + 2 * VBUF_SZ)
#define STAGE_STR 132

__global__ __launch_bounds__(256, 3) void attn_kernel(
    const float* __restrict__ x,
    const float* __restrict__ gamma,
    float* __restrict__ out)
{
    __shared__ __align__(16) char s_buf[SMEM_SZ];
    __shared__ float sinv_s[128];
    __shared__ int s_old;

    const int tid  = threadIdx.x;
    const int wid  = tid >> 5;
    const int lane = tid & 31;
    const int g    = lane >> 2;
    const int tg   = lane & 3;
    const int b    = blockIdx.y;
    const int sp   = blockIdx.z;
    const int qt   = blockIdx.x;
    const int qbase = qt * 128;

    const uint32_t sbase = smem_u32(s_buf);

    const int mat      = lane >> 3;
    const int row_lane = lane & 7;
    const uint32_t k_lm_off = (uint32_t)(((mat >> 1) * 8 + row_lane) * K_STR + (mat & 1) * 16);
    const uint32_t v_lm_off = (uint32_t)(((mat >> 1) * 8 + row_lane) * V_STR + (mat & 1) * 16);

    uint32_t qh_r0, qh_r1, ql_r0, ql_r1;
    {
        const int r0 = qbase + wid * 16 + g;
        float2 q0 = *(const float2*)(g_q + ((size_t)b * NSP + r0) * 8 + tg * 2);
        float2 q1 = *(const float2*)(g_q + ((size_t)b * NSP + r0 + 8) * 8 + tg * 2);
        uint16_t h0, l0, h1, l1;
        split_bf16(q0.x, h0, l0); split_bf16(q0.y, h1, l1);
        qh_r0 = (uint32_t)h0 | ((uint32_t)h1 << 16);
        ql_r0 = (uint32_t)l0 | ((uint32_t)l1 << 16);
        split_bf16(q1.x, h0, l0); split_bf16(q1.y, h1, l1);
        qh_r1 = (uint32_t)h0 | ((uint32_t)h1 << 16);
        ql_r1 = (uint32_t)l0 | ((uint32_t)l1 << 16);
    }

    float oc[8][4];
    #pragma unroll
    for (int t = 0; t < 8; t++)
        #pragma unroll
        for (int i = 0; i < 4; i++) oc[t][i] = 0.f;
    float lsum0 = 0.f, lsum1 = 0.f;

    const uint32_t* gk = g_kp + (size_t)b * NSP * 8;
    const __nv_bfloat16* gv = g_v + (size_t)b * CCH * NSP;

    const int k_key  = tid >> 1;
    const int k_part = tid & 1;
    auto load_tile = [&](int kt, int buf) {
        cp_async16(sbase + buf * KBUF_SZ + k_key * K_STR + k_part * 16,
                   gk + ((size_t)kt * KT + k_key) * 8 + k_part * 4);
        #pragma unroll
        for (int i = 0; i < 4; i++) {
            int idx = tid + i * 256;
            int c = idx >> 4, seg = idx & 15;
            cp_async16(sbase + VBASE + buf * VBUF_SZ + c * V_STR + seg * 16,
                       gv + (size_t)c * NSP + kt * KT + seg * 8);
        }
    };

    // uneven split: sp0 tiles [0,11), sp1 [11,22), sp2 [22,32)
    const int kt0 = sp * 11;
    const int n_tiles = (sp == 2) ? 10 : 11;

    load_tile(kt0, 0);
    CP_COMMIT();

    for (int it = 0; it < n_tiles; it++) {
        const int cur = it & 1;
        CP_WAIT0();
        __syncthreads();
        if (it + 1 < n_tiles) {
            load_tile(kt0 + it + 1, cur ^ 1);
            CP_COMMIT();
        }

        const uint32_t k_lm = sbase + cur * KBUF_SZ + k_lm_off;
        const uint32_t v_lm = sbase + VBASE + cur * VBUF_SZ + v_lm_off;

        float    sc[2][4][4];
        uint32_t pa[2][2][4];

        auto S = [&](int c, float scc[4][4]) {
            #pragma unroll
            for (int i = 0; i < 2; i++) {
                const int tp = 2 * c + i;
                uint32_t b00, b01, b10, b11;
                ldsm_x4(b00, b01, b10, b11, k_lm + (uint32_t)(tp * 16 * K_STR));
                #pragma unroll
                for (int j = 0; j < 4; j++) { scc[2*i][j] = 0.f; scc[2*i+1][j] = 0.f; }
                mma_16x8x16(scc[2*i],   qh_r0, qh_r1, qh_r0, qh_r1, b00, b01);
                mma_16x8x8 (scc[2*i],   ql_r0, ql_r1, b00);
                mma_16x8x16(scc[2*i+1], qh_r0, qh_r1, qh_r0, qh_r1, b10, b11);
                mma_16x8x8 (scc[2*i+1], ql_r0, ql_r1, b10);
            }
        };
        auto E = [&](float scc[4][4], uint32_t pac[2][4]) {
            #pragma unroll
            for (int i = 0; i < 2; i++) {
                float e00 = ex2f(scc[2*i][0]),   e01 = ex2f(scc[2*i][1]);
                float e02 = ex2f(scc[2*i][2]),   e03 = ex2f(scc[2*i][3]);
                float e10 = ex2f(scc[2*i+1][0]), e11 = ex2f(scc[2*i+1][1]);
                float e12 = ex2f(scc[2*i+1][2]), e13 = ex2f(scc[2*i+1][3]);
                lsum0 += (e00 + e01) + (e10 + e11);
                lsum1 += (e02 + e03) + (e12 + e13);
                pac[i][0] = cvt_bf16x2(e01, e00);
                pac[i][1] = cvt_bf16x2(e03, e02);
                pac[i][2] = cvt_bf16x2(e11, e10);
                pac[i][3] = cvt_bf16x2(e13, e12);
            }
        };
        auto O = [&](int c, uint32_t pac[2][4]) {
            #pragma unroll
            for (int i = 0; i < 2; i++) {
                const int kk = 2 * c + i;
                #pragma unroll
                for (int tp = 0; tp < 4; tp++) {
                    uint32_t b00, b01, b10, b11;
                    ldsm_x4(b00, b01, b10, b11,
                            v_lm + (uint32_t)(tp * 16 * V_STR + kk * 32));
                    mma_16x8x16(oc[2*tp],   pac[i][0], pac[i][1], pac[i][2], pac[i][3], b00, b01);
                    mma_16x8x16(oc[2*tp+1], pac[i][0], pac[i][1], pac[i][2], pac[i][3], b10, b11);
                }
            }
        };

        S(0, sc[0]);
        E(sc[0], pa[0]);
        #pragma unroll
        for (int c = 0; c < 4; c++) {
            const int curp = c & 1, nxt = curp ^ 1;
            if (c < 3) S(c + 1, sc[nxt]);
            O(c, pa[curp]);
            if (c < 3) E(sc[nxt], pa[nxt]);
        }
    }

    // ---- reduce lsum; publish partials to global ----
    lsum0 += __shfl_xor_sync(0xFFFFFFFF, lsum0, 1);
    lsum0 += __shfl_xor_sync(0xFFFFFFFF, lsum0, 2);
    lsum1 += __shfl_xor_sync(0xFFFFFFFF, lsum1, 1);
    lsum1 += __shfl_xor_sync(0xFFFFFFFF, lsum1, 2);
    const int pbase = ((sp * BATCH + b) * NQT + qt);
    if (tg == 0) {
        g_pl[pbase * 128 + wid * 16 + g]     = lsum0;
        g_pl[pbase * 128 + wid * 16 + g + 8] = lsum1;
    }

    __syncthreads();                       // tile reads done; reuse s_buf
    float* stage = (float*)s_buf;          // [64][STAGE_STR] unnormalized O
    const int n0 = wid * 16 + g;
    #pragma unroll
    for (int t = 0; t < 8; t++) {
        const int c = t * 8 + tg * 2;
        stage[c * STAGE_STR + n0]           = oc[t][0];
        stage[(c + 1) * STAGE_STR + n0]     = oc[t][1];
        stage[c * STAGE_STR + n0 + 8]       = oc[t][2];
        stage[(c + 1) * STAGE_STR + n0 + 8] = oc[t][3];
    }
    __syncthreads();

    float* po = g_po + (size_t)pbase * (CCH * 128);
    for (int idx = tid; idx < CCH * 128; idx += 256) {
        const int c  = idx >> 7;
        const int nn = idx & 127;
        po[idx] = stage[c * STAGE_STR + nn];
    }

    // ---- finisher election (threadfence + atomic, self-resetting) ----
    __threadfence();
    __syncthreads();
    if (tid == 0) s_old = atomicAdd(&g_sem[b * NQT + qt], 1);
    __syncthreads();
    if (s_old != NSPLIT - 1) return;       // non-last CTAs done
    if (tid == 0) g_sem[b * NQT + qt] = 0; // reset for graph replay

    // ---- combine all NSPLIT partials in FIXED sp order (deterministic) ----
    int p[NSPLIT];
    #pragma unroll
    for (int s = 0; s < NSPLIT; s++) p[s] = ((s * BATCH + b) * NQT + qt);

    if (tid < 128) {
        float l = 0.f;
        #pragma unroll
        for (int s = 0; s < NSPLIT; s++) l += g_pl[p[s] * 128 + tid];
        sinv_s[tid] = __ldg(gamma) / l;
    }
    __syncthreads();

    const size_t base = (size_t)b * CCH * NSP + (size_t)qt * 128;
    for (int idx = tid; idx < CCH * 128; idx += 256) {
        const int c  = idx >> 7;
        const int nn = idx & 127;
        float acc = 0.f;
        #pragma unroll
        for (int s = 0; s < NSPLIT; s++)
            acc += g_po[(size_t)p[s] * (CCH * 128) + idx];
        const size_t off = base + (size_t)c * NSP + nn;
        out[off] = x[off] + acc * sinv_s[nn];
    }
}

extern "C" void kernel_launch(void* const* d_in, const int* in_sizes, int n_in,
                              void* d_out, int out_size)
{
    const float* x     = (const float*)d_in[0];
    const float* wq    = (const float*)d_in[1];
    const float* bq    = (const float*)d_in[2];
    const float* wk    = (const float*)d_in[3];
    const float* bk    = (const float*)d_in[4];
    const float* wv    = (const float*)d_in[5];
    const float* bv    = (const float*)d_in[6];
    const float* gamma = (const float*)d_in[7];
    float* out = (float*)d_out;

    dim3 pg(NSP / 64, BATCH);
    proj_kernel<<<pg, 256>>>(x, wq, bq, wk, bk, wv, bv);

    dim3 ag(NQT, BATCH, NSPLIT);
    attn_kernel<<<ag, 256>>>(x, gamma, out);
}